// round 14
// baseline (speedup 1.0000x reference)
#include <cuda_runtime.h>
#include <math.h>

// ---------------------------------------------------------------------------
// Problem constants
// ---------------------------------------------------------------------------
#define N64    64
#define G      262144     // 64^3
#define KG     6
#define AK     768        // NATOM*KG
#define NS     33         // surviving frequencies per axis: s in [-16,16]
#define NLIVE  399        // live (ky,kz) half-columns: sy^2+sz^2 <= 256
#define SPLIT1 149        // blocks [0,149): 1 column; [149,274): 2 columns
#define NB     274        // persistent grid, 2 blocks/SM, all co-resident

// ---------------------------------------------------------------------------
// Device scratch (static globals: no allocation allowed)
// ---------------------------------------------------------------------------
__device__ float2 g_Ft[3 * N64 * AK];  // per-axis table DFTs, [axis][k][ak]
__device__ float2 g_A [17 * 64 * 34];  // weighted x-inverse: [kzs<=16][x][kys]
                                       // dead entries never written (zero-init)
__device__ double g_sum, g_sumsq;      // spectral-domain stats (Parseval)
__device__ unsigned int          g_cnt[2];
__device__ volatile unsigned int g_gen[2];

// Live half-column enumeration: row kzs spans [c_row0[kzs], c_row0[kzs+1]).
// Row widths (kzs=0..15): 1,11,15,19,21,23,25,27,27,29,29,31,31,31,31,31;
// kzs=16 holds 17 (kys=0..16). Total 399. L=398 is the DC column (16,16).
__constant__ int c_row0[18] =
    {0,1,12,27,46,67,90,115,142,169,198,227,258,289,320,351,382,399};

// Shared-memory union: phases strictly sequential (grid barriers between).
union SmemU {
    struct { float  R[8 * 64]; float2 T[8 * 34]; } a;    // phase A
    struct { float2 Fx[128 * 33];                        // phase B: [ak][kx]
             float2 P [2 * 128];
             float2 Sp[16 * NS];
             double Sred[2 * NS]; } b;
    struct { float2 A[17 * 33]; float2 C[17 * 16]; } c;  // phase C
};

// Replay-safe grid barrier (counter self-resets via atomicInc wrap).
__device__ __forceinline__ void gbar(int i)
{
    __threadfence();
    __syncthreads();
    if (threadIdx.x == 0) {
        unsigned int my = g_gen[i];
        unsigned int t = atomicInc(&g_cnt[i], NB - 1);
        if (t == NB - 1) { __threadfence(); g_gen[i] = my + 1; }
        else             { while (g_gen[i] == my) __nanosleep(64); }
        __threadfence();
    }
    __syncthreads();
}

// Complex dot body: A iterations, even/odd split accumulators.
// Fr stride 33 float2 (transposed Fx tile, lane = kx), Pr contiguous bcast.
template <int A>
__device__ __forceinline__ void dotb(const float2* __restrict__ Pr,
                                     const float2* __restrict__ Fr,
                                     float2& Sa, float2& Sb)
{
    #pragma unroll
    for (int a = 0; a < A; a += 2) {
        float2 p0 = Pr[a],     f0 = Fr[a * 33];
        float2 p1 = Pr[a + 1], f1 = Fr[(a + 1) * 33];
        Sa.x = fmaf(p0.x, f0.x, Sa.x); Sa.x = fmaf(-p0.y, f0.y, Sa.x);
        Sa.y = fmaf(p0.x, f0.y, Sa.y); Sa.y = fmaf( p0.y, f0.x, Sa.y);
        Sb.x = fmaf(p1.x, f1.x, Sb.x); Sb.x = fmaf(-p1.y, f1.y, Sb.x);
        Sb.y = fmaf(p1.x, f1.y, Sb.y); Sb.y = fmaf( p1.y, f1.x, Sb.y);
    }
}

// ---------------------------------------------------------------------------
// Whole pipeline, one persistent kernel, 2 blocks/SM (regs capped at 64).
// ---------------------------------------------------------------------------
__global__ void __launch_bounds__(512, 2)
k_all(const float* __restrict__ X,  const float* __restrict__ aw,
      const float* __restrict__ bw, const float* __restrict__ rgf,
      const float* __restrict__ ham, float* __restrict__ out)
{
    __shared__ SmemU U;
    __shared__ float2 Wsh[64];
    __shared__ int   colKys[2], colKzs[2], colKyi[2], colKzi[2];
    __shared__ float colWt[2];

    int tid = threadIdx.x, bid = blockIdx.x;

    if (tid < 64) {
        float ang = -2.0f * 3.14159265358979323846f * (float)tid / 64.0f;
        float s, c;
        __sincosf(ang, &s, &c);
        Wsh[tid] = make_float2(c, s);
    }
    if (bid == 0 && tid == 0) g_sumsq = 0.0;
    __syncthreads();

    // ===== Phase A: tables -> 17-pt real DFT (+conj mirror) -> g_Ft =========
    {
        int r_e = tid >> 6, n_e = tid & 63;
        for (int gg = bid; gg < 288; gg += NB) {     // 8 same-axis rows/group
            int row  = gg * 8 + r_e;
            int axis = row / 768;
            int ak   = row - axis * 768;
            int a    = ak / KG;
            int kk   = ak - a * KG;
            float b  = bw[a * KG + kk];
            float wc = aw[a * KG + kk];
            float cc = (axis == 0) ? rgf[n_e * 12288]
                     : (axis == 1) ? rgf[n_e * 192 + 1]
                                   : rgf[n_e * 3 + 2];
            float d  = cc - X[a * 3 + axis];
            float v  = __expf(b * d * d);
            if (axis == 0) v *= wc;
            U.a.R[r_e * 64 + n_e] = v;
            __syncthreads();
            if (tid < 136) {                         // 8 rows x 17 k-values
                int r = tid / 17, k = tid - r * 17;
                float2 ae = make_float2(0.f, 0.f), ao = ae;
                #pragma unroll
                for (int m = 0; m < 64; m += 2) {
                    float  x0 = U.a.R[r * 64 + m];
                    float  x1 = U.a.R[r * 64 + m + 1];
                    float2 w0 = Wsh[(k * m) & 63];
                    float2 w1 = Wsh[(k * (m + 1)) & 63];
                    ae.x = fmaf(x0, w0.x, ae.x); ae.y = fmaf(x0, w0.y, ae.y);
                    ao.x = fmaf(x1, w1.x, ao.x); ao.y = fmaf(x1, w1.y, ao.y);
                }
                U.a.T[r * 34 + k] = make_float2(ae.x + ao.x, ae.y + ao.y);
            }
            __syncthreads();
            if (tid < 264) {    // coalesced stores: 33 used k slots x 8 aks
                int j = tid >> 3, dak = tid & 7;     // j = 0..32
                int axis0 = gg / 96;                 // 96 groups per axis
                int akb   = gg * 8 - axis0 * 768;
                float2 t; int ks;
                if (j <= 16) { t = U.a.T[dak * 34 + j]; ks = j; }
                else {                               // k = j+31 in 48..63
                    float2 s = U.a.T[dak * 34 + (33 - j)];
                    t = make_float2(s.x, -s.y); ks = j + 31;
                }
                g_Ft[axis0 * (N64 * AK) + ks * AK + akb + dak] = t;
            }
            __syncthreads();
        }
    }
    gbar(0);

    // ===== Phase B: live-column spectrum + Hamming + weighted x-inverse =====
    {
        int NC, Lbase;
        if (bid < SPLIT1) { NC = 1; Lbase = bid; }               // L 0..148
        else { NC = 2; Lbase = SPLIT1 + (bid - SPLIT1) * 2; }    // L 149..398
        if (tid < NC) {
            int L = Lbase + tid;
            int kzs = 0;
            while (c_row0[kzs + 1] <= L) kzs++;
            int off = L - c_row0[kzs];
            int w   = c_row0[kzs + 1] - c_row0[kzs];
            int kys = (kzs == 16) ? off : (16 - (w - 1) / 2 + off);
            colKys[tid] = kys;             colKzs[tid] = kzs;
            colKyi[tid] = (kys - 16) & 63; colKzi[tid] = (kzs - 16) & 63;
            colWt[tid]  = (L == NLIVE - 1) ? 1.f : 2.f;   // Hermitian weight
        }
        __syncthreads();

        int w    = tid >> 5, lane = tid & 31;
        int wsl  = (NC == 1) ? 4 : 3;        // warps/col = 16 or 8
        int colw = w >> wsl;
        int q    = w & ((1 << wsl) - 1);
        int AKW  = 128 >> wsl;               // 8 or 16 ak per warp per chunk
        float2 Sa = make_float2(0.f, 0.f), Sb = Sa, S2 = Sa;

        for (int ch = 0; ch < 6; ch++) {
            int ak0 = ch * 128;
            for (int i = tid; i < 33 * 128; i += 512) {   // Fx -> [ak][kx]
                int kxc = i >> 7, a = i & 127;
                int kxi = (kxc - 16) & 63;
                U.b.Fx[a * 33 + kxc] = g_Ft[kxi * AK + ak0 + a];
            }
            for (int i = tid; i < NC * 128; i += 512) {   // P = Fy*Fz
                int col = i >> 7, a = i & 127;
                float2 fa = g_Ft[N64 * AK     + colKyi[col] * AK + ak0 + a];
                float2 fb = g_Ft[2 * N64 * AK + colKzi[col] * AK + ak0 + a];
                U.b.P[i] = make_float2(fa.x * fb.x - fa.y * fb.y,
                                       fa.x * fb.y + fa.y * fb.x);
            }
            __syncthreads();
            {
                const float2* Pr = &U.b.P[colw * 128 + q * AKW];
                const float2* Fr = &U.b.Fx[(q * AKW) * 33 + lane];
                if (NC == 1) dotb<8> (Pr, Fr, Sa, Sb);
                else         dotb<16>(Pr, Fr, Sa, Sb);
                if (lane < AKW) {                         // kx = 32 slice
                    float2 p = Pr[lane];
                    float2 f = U.b.Fx[(q * AKW + lane) * 33 + 32];
                    S2.x = fmaf(p.x, f.x, S2.x); S2.x = fmaf(-p.y, f.y, S2.x);
                    S2.y = fmaf(p.x, f.y, S2.y); S2.y = fmaf( p.y, f.x, S2.y);
                }
            }
            __syncthreads();
        }
        #pragma unroll
        for (int o = 16; o; o >>= 1) {
            S2.x += __shfl_xor_sync(0xFFFFFFFFu, S2.x, o);
            S2.y += __shfl_xor_sync(0xFFFFFFFFu, S2.y, o);
        }
        U.b.Sp[w * NS + lane] = make_float2(Sa.x + Sb.x, Sa.y + Sb.y);
        if (lane == 0) U.b.Sp[w * NS + 32] = S2;
        __syncthreads();

        // combine warp partials per column + Hamming + Parseval stats
        int WPC = 1 << wsl;
        float2 v = make_float2(0.f, 0.f);
        int colc = 0, sxsc = 0;
        if (tid < NC * NS) {
            colc = tid / NS; sxsc = tid - colc * NS;
            float2 acc = make_float2(0.f, 0.f);
            for (int i = 0; i < WPC; i++) {
                float2 t = U.b.Sp[(colc * WPC + i) * NS + sxsc];
                acc.x += t.x; acc.y += t.y;
            }
            int kys = colKys[colc], kzs = colKzs[colc];
            int hx = (sxsc + 16) & 63, hy = (kys + 16) & 63, hz = (kzs + 16) & 63;
            float h = ham[(hx << 12) | (hy << 6) | hz];
            v = make_float2(acc.x * h, acc.y * h);
            int L = Lbase + colc;
            double m2 = (double)v.x * v.x + (double)v.y * v.y;
            U.b.Sred[tid] = (L == NLIVE - 1) ? m2 : 2.0 * m2;   // Hermitian wt
            if (L == NLIVE - 1 && sxsc == 16) g_sum = (double)v.x;  // S(0,0,0)
        }
        __syncthreads();
        if (tid < NC * NS) U.b.Sp[colc * NS + sxsc] = v;
        if (tid == 0) {
            double t = 0.0;
            for (int i = 0; i < NC * NS; i++) t += U.b.Sred[i];
            atomicAdd(&g_sumsq, t);
        }
        __syncthreads();

        // fused x-inverse (rotation twiddles), Hermitian weight pre-folded
        if (tid < NC * 64) {
            int col = tid >> 6, x = tid & 63;
            float2 T  = make_float2(0.f, 0.f);
            float2 wv = Wsh[(16 * x) & 63];      // s = -16 start
            float2 ws = Wsh[(-x) & 63];          // step: * e^{+2pi i x/64}
            #pragma unroll
            for (int sxs = 0; sxs < NS; sxs++) {
                float2 s = U.b.Sp[col * NS + sxs];
                T.x = fmaf(s.x, wv.x, T.x); T.x = fmaf(-s.y, wv.y, T.x);
                T.y = fmaf(s.x, wv.y, T.y); T.y = fmaf( s.y, wv.x, T.y);
                float2 nw = make_float2(wv.x * ws.x - wv.y * ws.y,
                                        wv.x * ws.y + wv.y * ws.x);
                wv = nw;
            }
            float wt = colWt[col];
            g_A[colKzs[col] * 2176 + x * 34 + colKys[col]] =
                make_float2(T.x * wt, T.y * wt);
        }
    }
    gbar(1);

    // ===== Phase C: folded half-plane y/z-inverse + normalized write ========
    // 256 units: (x, y-quarter of 16).
    // out = Re sum_{kzs=0..16} C[kzs][y] e^{+2pi i z (kzs-16)/64},
    // C[kzs][y] = sum_kys Aw[kzs][kys] e^{+2pi i y (kys-16)/64}  (Aw weighted)
    if (bid < 256) {
        int x = bid >> 2, yq = bid & 3;
        for (int i = tid; i < 17 * 33; i += 512) {
            int kzs = i / 33, kys = i - kzs * 33;
            U.c.A[i] = g_A[kzs * 2176 + x * 34 + kys];
        }
        __syncthreads();

        if (tid < 17 * 16) {                 // y-inverse (272 entries)
            int yl = tid & 15, kzs = tid >> 4;
            int y  = yq * 16 + yl;
            float2 acc = make_float2(0.f, 0.f);
            float2 wv  = Wsh[(16 * y) & 63];
            float2 ws  = Wsh[(-y) & 63];
            #pragma unroll
            for (int kys = 0; kys < NS; kys++) {
                float2 a = U.c.A[kzs * 33 + kys];
                acc.x = fmaf(a.x, wv.x, acc.x); acc.x = fmaf(-a.y, wv.y, acc.x);
                acc.y = fmaf(a.x, wv.y, acc.y); acc.y = fmaf( a.y, wv.x, acc.y);
                float2 nw = make_float2(wv.x * ws.x - wv.y * ws.y,
                                        wv.x * ws.y + wv.y * ws.x);
                wv = nw;
            }
            U.c.C[kzs * 16 + yl] = acc;
        }
        __syncthreads();

        // Parseval stats: mean = S[0]/G;  E[out^2] = sum|S|^2 / G^2
        double mean = g_sum / (double)G;
        double var  = g_sumsq / ((double)G * (double)G) - mean * mean;
        double stdv = sqrt(var > 0.0 ? var : 0.0);
        float  inv  = (float)(1.0 / (stdv + 1e-8));
        float  m    = (float)mean;

        int z = tid & 63, yg = tid >> 6;     // 8 y-groups of 2
        float acc2[2];
        acc2[0] = 0.f; acc2[1] = 0.f;
        float2 wv = Wsh[(16 * z) & 63];
        float2 ws = Wsh[(-z) & 63];
        for (int kzs = 0; kzs <= 16; kzs++) {        // folded z-inverse, Re
            #pragma unroll
            for (int j = 0; j < 2; j++) {
                float2 c = U.c.C[kzs * 16 + yg * 2 + j];
                acc2[j] = fmaf(c.x, wv.x, acc2[j]);
                acc2[j] = fmaf(-c.y, wv.y, acc2[j]);
            }
            float2 nw = make_float2(wv.x * ws.x - wv.y * ws.y,
                                    wv.x * ws.y + wv.y * ws.x);
            wv = nw;
        }
        const float scale = 1.0f / 262144.0f;        // ortho*ortho = 1/N^3
        #pragma unroll
        for (int j = 0; j < 2; j++) {
            float vv = acc2[j] * scale;
            int y = yq * 16 + yg * 2 + j;
            out[x * 4096 + y * 64 + z] = (vv - m) * inv;
        }
    }
}

// ---------------------------------------------------------------------------
// Launch
//   inputs: 0=X(384) 1=aw(768) 2=bw(768) 3=real_grid_flat(786432) 4=hamming(262144)
// ---------------------------------------------------------------------------
extern "C" void kernel_launch(void* const* d_in, const int* in_sizes, int n_in,
                              void* d_out, int out_size)
{
    const float* X   = (const float*)d_in[0];
    const float* aw  = (const float*)d_in[1];
    const float* bw  = (const float*)d_in[2];
    const float* rgf = (const float*)d_in[3];
    const float* ham = (const float*)d_in[4];

    k_all<<<NB, 512>>>(X, aw, bw, rgf, ham, (float*)d_out);
}

// round 15
// speedup vs baseline: 1.0998x; 1.0998x over previous
#include <cuda_runtime.h>
#include <math.h>

// ---------------------------------------------------------------------------
// Problem constants
// ---------------------------------------------------------------------------
#define N64    64
#define G      262144     // 64^3
#define KG     6
#define AK     768        // NATOM*KG
#define NS     33         // surviving frequencies per axis: s in [-16,16]
#define NLIVE  399        // live (ky,kz) half-columns: sy^2+sz^2 <= 256
#define NB     137        // persistent grid, 1 block/SM, all co-resident

// ---------------------------------------------------------------------------
// Device scratch (static globals: no allocation allowed)
// ---------------------------------------------------------------------------
__device__ float2 g_FtX[AK * 34];      // x-axis DFT, TRANSPOSED: [ak][sxs 0..32]
__device__ float2 g_Ft [2 * N64 * AK]; // y,z-axis DFTs: [axis][k][ak]
__device__ float2 g_A  [17 * 64 * 34]; // weighted x-inverse: [kzs<=16][x][kys]
                                       // dead entries never written (zero-init)
__device__ double g_sum, g_sumsq;      // spectral-domain stats (Parseval)
__device__ unsigned int          g_cnt[2];
__device__ volatile unsigned int g_gen[2];

// Live half-column enumeration: row kzs spans [c_row0[kzs], c_row0[kzs+1]).
// Row widths (kzs=0..15): 1,11,15,19,21,23,25,27,27,29,29,31,31,31,31,31;
// kzs=16 holds 17 (kys=0..16). Total 399. L=398 is the DC column (16,16).
__constant__ int c_row0[18] =
    {0,1,12,27,46,67,90,115,142,169,198,227,258,289,320,351,382,399};

// Shared-memory union: phases strictly sequential (grid barriers between).
union SmemU {
    struct { float  R[16 * 64]; float2 T[16 * 34]; } a;  // phase A
    struct { float2 P [4 * 768];                         // phase B: [col][ak]
             float2 Sp[16 * NS];
             double Sred[4 * NS]; } b;
    struct { float2 A[17 * 33]; float2 C[17 * 32]; } c;  // phase C
};

// Replay-safe grid barrier (counter self-resets via atomicInc wrap).
__device__ __forceinline__ void gbar(int i)
{
    __threadfence();
    __syncthreads();
    if (threadIdx.x == 0) {
        unsigned int my = g_gen[i];
        unsigned int t = atomicInc(&g_cnt[i], NB - 1);
        if (t == NB - 1) { __threadfence(); g_gen[i] = my + 1; }
        else             { while (g_gen[i] == my) __nanosleep(64); }
        __threadfence();
    }
    __syncthreads();
}

// Direct-from-global complex dot: AKPW aks, Fx coalesced (stride 34 rows,
// lane = kx slot), P broadcast from shared. Even/odd split accumulators.
template <int AKPW>
__device__ __forceinline__ void dotg(const float2* __restrict__ Pr,
                                     const float2* __restrict__ Fr,
                                     float2& Sa, float2& Sb)
{
    #pragma unroll 8
    for (int i = 0; i < AKPW; i += 2) {
        float2 f0 = Fr[i * 34],      p0 = Pr[i];
        float2 f1 = Fr[(i + 1) * 34], p1 = Pr[i + 1];
        Sa.x = fmaf(p0.x, f0.x, Sa.x); Sa.x = fmaf(-p0.y, f0.y, Sa.x);
        Sa.y = fmaf(p0.x, f0.y, Sa.y); Sa.y = fmaf( p0.y, f0.x, Sa.y);
        Sb.x = fmaf(p1.x, f1.x, Sb.x); Sb.x = fmaf(-p1.y, f1.y, Sb.x);
        Sb.y = fmaf(p1.x, f1.y, Sb.y); Sb.y = fmaf( p1.y, f1.x, Sb.y);
    }
}

// ---------------------------------------------------------------------------
// Whole pipeline, one persistent kernel, 1 block/SM (no register cap).
// ---------------------------------------------------------------------------
__global__ void __launch_bounds__(512, 1)
k_all(const float* __restrict__ X,  const float* __restrict__ aw,
      const float* __restrict__ bw, const float* __restrict__ rgf,
      const float* __restrict__ ham, float* __restrict__ out)
{
    __shared__ SmemU U;
    __shared__ float2 Wsh[64];
    __shared__ int   colKys[4], colKzs[4], colKyi[4], colKzi[4];
    __shared__ float colWt[4];

    int tid = threadIdx.x, bid = blockIdx.x;

    if (tid < 64) {
        float ang = -2.0f * 3.14159265358979323846f * (float)tid / 64.0f;
        float s, c;
        __sincosf(ang, &s, &c);
        Wsh[tid] = make_float2(c, s);
    }
    if (bid == 0 && tid == 0) g_sumsq = 0.0;
    __syncthreads();

    // ===== Phase A: tables -> 17-pt real DFT -> g_FtX / g_Ft ================
    // 144 groups of 16 same-axis rows (48 groups per axis).
    {
        for (int gg = bid; gg < 144; gg += NB) {
            int axis = gg / 48;
            int ak0  = (gg - axis * 48) * 16;
            for (int i = tid; i < 1024; i += 512) {      // exp: 16 rows x 64
                int r_e = i >> 6, n_e = i & 63;
                int ak  = ak0 + r_e;
                int a   = ak / KG;
                int kk  = ak - a * KG;
                float b  = bw[a * KG + kk];
                float wc = aw[a * KG + kk];
                float cc = (axis == 0) ? rgf[n_e * 12288]
                         : (axis == 1) ? rgf[n_e * 192 + 1]
                                       : rgf[n_e * 3 + 2];
                float d  = cc - X[a * 3 + axis];
                float v  = __expf(b * d * d);
                if (axis == 0) v *= wc;
                U.a.R[r_e * 64 + n_e] = v;
            }
            __syncthreads();
            if (tid < 272) {                             // 16 rows x 17 k
                int r = tid / 17, k = tid - r * 17;
                float2 ae = make_float2(0.f, 0.f), ao = ae;
                #pragma unroll
                for (int m = 0; m < 64; m += 2) {
                    float  x0 = U.a.R[r * 64 + m];
                    float  x1 = U.a.R[r * 64 + m + 1];
                    float2 w0 = Wsh[(k * m) & 63];
                    float2 w1 = Wsh[(k * (m + 1)) & 63];
                    ae.x = fmaf(x0, w0.x, ae.x); ae.y = fmaf(x0, w0.y, ae.y);
                    ao.x = fmaf(x1, w1.x, ao.x); ao.y = fmaf(x1, w1.y, ao.y);
                }
                U.a.T[r * 34 + k] = make_float2(ae.x + ao.x, ae.y + ao.y);
            }
            __syncthreads();
            // stores: 33 slots x 16 rows = 528 entries
            for (int i = tid; i < 528; i += 512) {
                if (axis == 0) {        // transposed centered: [ak][sxs]
                    int dak = i / 33, j = i - dak * 33;  // j = sxs
                    float2 t;
                    if (j >= 16) t = U.a.T[dak * 34 + (j - 16)];
                    else {
                        float2 s = U.a.T[dak * 34 + (16 - j)];
                        t = make_float2(s.x, -s.y);
                    }
                    g_FtX[(ak0 + dak) * 34 + j] = t;
                } else {                // [k][ak] with conj mirror
                    int dak = i & 15, j = i >> 4;        // j = 0..32
                    float2 t; int ks;
                    if (j <= 16) { t = U.a.T[dak * 34 + j]; ks = j; }
                    else {
                        float2 s = U.a.T[dak * 34 + (33 - j)];
                        t = make_float2(s.x, -s.y); ks = j + 31;
                    }
                    g_Ft[(axis - 1) * (N64 * AK) + ks * AK + ak0 + dak] = t;
                }
            }
            __syncthreads();
        }
    }
    gbar(0);

    // ===== Phase B: live-column spectrum + Hamming + weighted x-inverse =====
    {
        int NC, Lbase;
        if (bid < 74) { NC = 2; Lbase = bid * 2; }           // L 0..147
        else          { NC = 4; Lbase = 148 + (bid - 74) * 4; } // L 148..399
        if (tid < NC) {
            int L = Lbase + tid; if (L > NLIVE - 1) L = NLIVE - 1;
            int kzs = 0;
            while (c_row0[kzs + 1] <= L) kzs++;
            int off = L - c_row0[kzs];
            int w   = c_row0[kzs + 1] - c_row0[kzs];
            int kys = (kzs == 16) ? off : (16 - (w - 1) / 2 + off);
            colKys[tid] = kys;             colKzs[tid] = kzs;
            colKyi[tid] = (kys - 16) & 63; colKzi[tid] = (kzs - 16) & 63;
            colWt[tid]  = (L == NLIVE - 1) ? 1.f : 2.f;   // Hermitian weight
        }
        __syncthreads();

        // P = Fy * Fz staged once (coalesced global reads)
        for (int i = tid; i < NC * 768; i += 512) {
            int col = i / 768, a = i - col * 768;
            float2 fa = g_Ft[colKyi[col] * AK + a];
            float2 fb = g_Ft[N64 * AK + colKzi[col] * AK + a];
            U.b.P[col * 768 + a] = make_float2(fa.x * fb.x - fa.y * fb.y,
                                               fa.x * fb.y + fa.y * fb.x);
        }
        __syncthreads();

        int w    = tid >> 5, lane = tid & 31;
        int wsl  = (NC == 2) ? 3 : 2;        // warps/col = 8 or 4
        int colw = w >> wsl;
        int q    = w & ((1 << wsl) - 1);
        int akpw = 768 >> wsl;               // 96 or 192 aks per warp
        int base = q * akpw;
        float2 Sa = make_float2(0.f, 0.f), Sb = Sa, S2 = Sa;

        {
            const float2* Pr = &U.b.P[colw * 768 + base];
            const float2* Fr = &g_FtX[base * 34 + lane];
            if (NC == 2) dotg<96> (Pr, Fr, Sa, Sb);
            else         dotg<192>(Pr, Fr, Sa, Sb);
            // sxs = 32 slice, lane-parallel over this warp's ak range
            for (int i = lane; i < akpw; i += 32) {
                float2 f = g_FtX[(base + i) * 34 + 32];
                float2 p = U.b.P[colw * 768 + base + i];
                S2.x = fmaf(p.x, f.x, S2.x); S2.x = fmaf(-p.y, f.y, S2.x);
                S2.y = fmaf(p.x, f.y, S2.y); S2.y = fmaf( p.y, f.x, S2.y);
            }
        }
        #pragma unroll
        for (int o = 16; o; o >>= 1) {
            S2.x += __shfl_xor_sync(0xFFFFFFFFu, S2.x, o);
            S2.y += __shfl_xor_sync(0xFFFFFFFFu, S2.y, o);
        }
        U.b.Sp[w * NS + lane] = make_float2(Sa.x + Sb.x, Sa.y + Sb.y);
        if (lane == 0) U.b.Sp[w * NS + 32] = S2;
        __syncthreads();

        // combine warp partials per column + Hamming + Parseval stats
        int WPC = 1 << wsl;
        float2 v = make_float2(0.f, 0.f);
        int colc = 0, sxsc = 0;
        if (tid < NC * NS) {
            colc = tid / NS; sxsc = tid - colc * NS;
            float2 acc = make_float2(0.f, 0.f);
            for (int i = 0; i < WPC; i++) {
                float2 t = U.b.Sp[(colc * WPC + i) * NS + sxsc];
                acc.x += t.x; acc.y += t.y;
            }
            int kys = colKys[colc], kzs = colKzs[colc];
            int hx = (sxsc + 16) & 63, hy = (kys + 16) & 63, hz = (kzs + 16) & 63;
            float h = ham[(hx << 12) | (hy << 6) | hz];
            v = make_float2(acc.x * h, acc.y * h);
            int slotL = Lbase + colc;                 // un-clamped: stats guard
            double contrib = 0.0;
            if (slotL < NLIVE) {
                double m2 = (double)v.x * v.x + (double)v.y * v.y;
                contrib = (slotL == NLIVE - 1) ? m2 : 2.0 * m2;
                if (slotL == NLIVE - 1 && sxsc == 16) g_sum = (double)v.x;
            }
            U.b.Sred[tid] = contrib;
        }
        __syncthreads();
        if (tid < NC * NS) U.b.Sp[colc * NS + sxsc] = v;
        if (tid == 0) {
            double t = 0.0;
            for (int i = 0; i < NC * NS; i++) t += U.b.Sred[i];
            atomicAdd(&g_sumsq, t);
        }
        __syncthreads();

        // fused x-inverse (rotation twiddles), Hermitian weight pre-folded
        if (tid < NC * 64) {
            int col = tid >> 6, x = tid & 63;
            float2 T  = make_float2(0.f, 0.f);
            float2 wv = Wsh[(16 * x) & 63];      // s = -16 start
            float2 ws = Wsh[(-x) & 63];          // step: * e^{+2pi i x/64}
            #pragma unroll
            for (int sxs = 0; sxs < NS; sxs++) {
                float2 s = U.b.Sp[col * NS + sxs];
                T.x = fmaf(s.x, wv.x, T.x); T.x = fmaf(-s.y, wv.y, T.x);
                T.y = fmaf(s.x, wv.y, T.y); T.y = fmaf( s.y, wv.x, T.y);
                float2 nw = make_float2(wv.x * ws.x - wv.y * ws.y,
                                        wv.x * ws.y + wv.y * ws.x);
                wv = nw;
            }
            float wt = colWt[col];
            g_A[colKzs[col] * 2176 + x * 34 + colKys[col]] =
                make_float2(T.x * wt, T.y * wt);
        }
    }
    gbar(1);

    // ===== Phase C: folded half-plane y/z-inverse + normalized write ========
    // out = Re sum_{kzs=0..16} C[kzs][y] e^{+2pi i z (kzs-16)/64},
    // C[kzs][y] = sum_kys Aw[kzs][kys] e^{+2pi i y (kys-16)/64}  (Aw weighted)
    if (bid < 128) {
        int x = bid >> 1, yh = bid & 1;
        for (int i = tid; i < 17 * 33; i += 512) {
            int kzs = i / 33, kys = i - kzs * 33;
            U.c.A[i] = g_A[kzs * 2176 + x * 34 + kys];
        }
        __syncthreads();

        for (int i = tid; i < 17 * 32; i += 512) {   // y-inverse (544 entries)
            int yl = i & 31, kzs = i >> 5;
            int y  = yh * 32 + yl;
            float2 acc = make_float2(0.f, 0.f);
            float2 wv  = Wsh[(16 * y) & 63];
            float2 ws  = Wsh[(-y) & 63];
            #pragma unroll
            for (int kys = 0; kys < NS; kys++) {
                float2 a = U.c.A[kzs * 33 + kys];
                acc.x = fmaf(a.x, wv.x, acc.x); acc.x = fmaf(-a.y, wv.y, acc.x);
                acc.y = fmaf(a.x, wv.y, acc.y); acc.y = fmaf( a.y, wv.x, acc.y);
                float2 nw = make_float2(wv.x * ws.x - wv.y * ws.y,
                                        wv.x * ws.y + wv.y * ws.x);
                wv = nw;
            }
            U.c.C[kzs * 32 + yl] = acc;
        }
        __syncthreads();

        // Parseval stats: mean = S[0]/G;  E[out^2] = sum|S|^2 / G^2
        double mean = g_sum / (double)G;
        double var  = g_sumsq / ((double)G * (double)G) - mean * mean;
        double stdv = sqrt(var > 0.0 ? var : 0.0);
        float  inv  = (float)(1.0 / (stdv + 1e-8));
        float  m    = (float)mean;

        int z = tid & 63, yg = tid >> 6;     // 8 y-groups of 4
        float acc4[4];
        #pragma unroll
        for (int j = 0; j < 4; j++) acc4[j] = 0.f;
        float2 wv = Wsh[(16 * z) & 63];
        float2 ws = Wsh[(-z) & 63];
        for (int kzs = 0; kzs <= 16; kzs++) {        // folded z-inverse, Re
            #pragma unroll
            for (int j = 0; j < 4; j++) {
                float2 c = U.c.C[kzs * 32 + yg * 4 + j];
                acc4[j] = fmaf(c.x, wv.x, acc4[j]);
                acc4[j] = fmaf(-c.y, wv.y, acc4[j]);
            }
            float2 nw = make_float2(wv.x * ws.x - wv.y * ws.y,
                                    wv.x * ws.y + wv.y * ws.x);
            wv = nw;
        }
        const float scale = 1.0f / 262144.0f;        // ortho*ortho = 1/N^3
        #pragma unroll
        for (int j = 0; j < 4; j++) {
            float vv = acc4[j] * scale;
            int y = yh * 32 + yg * 4 + j;
            out[x * 4096 + y * 64 + z] = (vv - m) * inv;
        }
    }
}

// ---------------------------------------------------------------------------
// Launch
//   inputs: 0=X(384) 1=aw(768) 2=bw(768) 3=real_grid_flat(786432) 4=hamming(262144)
// ---------------------------------------------------------------------------
extern "C" void kernel_launch(void* const* d_in, const int* in_sizes, int n_in,
                              void* d_out, int out_size)
{
    const float* X   = (const float*)d_in[0];
    const float* aw  = (const float*)d_in[1];
    const float* bw  = (const float*)d_in[2];
    const float* rgf = (const float*)d_in[3];
    const float* ham = (const float*)d_in[4];

    k_all<<<NB, 512>>>(X, aw, bw, rgf, ham, (float*)d_out);
}

// round 16
// speedup vs baseline: 1.1427x; 1.0390x over previous
#include <cuda_runtime.h>
#include <math.h>

// ---------------------------------------------------------------------------
// Problem constants
// ---------------------------------------------------------------------------
#define N64    64
#define G      262144     // 64^3
#define KG     6
#define AK     768        // NATOM*KG
#define NS     33         // surviving frequencies per axis: s in [-16,16]
#define NLIVE  399        // live (ky,kz) half-columns: sy^2+sz^2 <= 256
#define NB     137        // persistent grid, 1 block/SM, all co-resident

// ---------------------------------------------------------------------------
// Device scratch (static globals: no allocation allowed)
// ---------------------------------------------------------------------------
__device__ float2 g_FtX[AK * 34];      // x-axis DFT, TRANSPOSED: [ak][sxs 0..32]
__device__ float2 g_Ft [2 * N64 * AK]; // y,z-axis DFTs: [axis][k][ak]
__device__ float2 g_A  [17 * 64 * 34]; // weighted x-inverse: [kzs<=16][x][kys]
                                       // dead entries never written (zero-init)
__device__ double g_sum, g_sumsq;      // spectral-domain stats (Parseval)
__device__ unsigned int          g_cnt[2];
__device__ volatile unsigned int g_gen[2];

// Live half-column enumeration: row kzs spans [c_row0[kzs], c_row0[kzs+1]).
// Row widths (kzs=0..15): 1,11,15,19,21,23,25,27,27,29,29,31,31,31,31,31;
// kzs=16 holds 17 (kys=0..16). Total 399. L=398 is the DC column (16,16).
__constant__ int c_row0[18] =
    {0,1,12,27,46,67,90,115,142,169,198,227,258,289,320,351,382,399};

// Shared-memory union: phases strictly sequential (grid barriers between).
union SmemU {
    struct { float  R[16 * 64]; float2 T[16 * 34]; } a;  // phase A
    struct { float2 P [4 * 768];                         // phase B: [col][ak]
             float2 Sp[16 * 66];    // per-warp partials: [w][colInPair][33]
             double Sred[4 * NS]; } b;
    struct { float2 A[17 * 33]; float2 C[17 * 32]; } c;  // phase C
};

// Replay-safe grid barrier (counter self-resets via atomicInc wrap).
__device__ __forceinline__ void gbar(int i)
{
    __threadfence();
    __syncthreads();
    if (threadIdx.x == 0) {
        unsigned int my = g_gen[i];
        unsigned int t = atomicInc(&g_cnt[i], NB - 1);
        if (t == NB - 1) { __threadfence(); g_gen[i] = my + 1; }
        else             { while (g_gen[i] == my) __nanosleep(64); }
        __threadfence();
    }
    __syncthreads();
}

#define CMAC(S, p, f)                                             \
    do {                                                          \
        (S).x = fmaf((p).x, (f).x, (S).x);                        \
        (S).x = fmaf(-(p).y, (f).y, (S).x);                       \
        (S).y = fmaf((p).x, (f).y, (S).y);                        \
        (S).y = fmaf((p).y, (f).x, (S).y);                        \
    } while (0)

// Dual-column complex dot: AKPW aks, ONE Fx load stream (coalesced,
// stride-34 rows, lane = kx slot) feeds TWO column accumulations.
// Four independent chains: (col0,col1) x (even,odd ak).
template <int AKPW>
__device__ __forceinline__ void dot2(const float2* __restrict__ P0,
                                     const float2* __restrict__ P1,
                                     const float2* __restrict__ Fr,
                                     float2& Sa0, float2& Sb0,
                                     float2& Sa1, float2& Sb1)
{
    #pragma unroll 4
    for (int i = 0; i < AKPW; i += 2) {
        float2 f0 = Fr[i * 34], f1 = Fr[(i + 1) * 34];
        float2 p00 = P0[i], p01 = P0[i + 1];
        float2 p10 = P1[i], p11 = P1[i + 1];
        CMAC(Sa0, p00, f0); CMAC(Sb0, p01, f1);
        CMAC(Sa1, p10, f0); CMAC(Sb1, p11, f1);
    }
}

// ---------------------------------------------------------------------------
// Whole pipeline, one persistent kernel, 1 block/SM (no register cap).
// ---------------------------------------------------------------------------
__global__ void __launch_bounds__(512, 1)
k_all(const float* __restrict__ X,  const float* __restrict__ aw,
      const float* __restrict__ bw, const float* __restrict__ rgf,
      const float* __restrict__ ham, float* __restrict__ out)
{
    __shared__ SmemU U;
    __shared__ float2 Wsh[64];
    __shared__ int   colKys[4], colKzs[4], colKyi[4], colKzi[4];
    __shared__ float colWt[4];

    int tid = threadIdx.x, bid = blockIdx.x;

    if (tid < 64) {
        float ang = -2.0f * 3.14159265358979323846f * (float)tid / 64.0f;
        float s, c;
        __sincosf(ang, &s, &c);
        Wsh[tid] = make_float2(c, s);
    }
    if (bid == 0 && tid == 0) g_sumsq = 0.0;
    __syncthreads();

    // ===== Phase A: tables -> 17-pt real DFT -> g_FtX / g_Ft ================
    // 144 groups of 16 same-axis rows (48 groups per axis).
    {
        for (int gg = bid; gg < 144; gg += NB) {
            int axis = gg / 48;
            int ak0  = (gg - axis * 48) * 16;
            for (int i = tid; i < 1024; i += 512) {      // exp: 16 rows x 64
                int r_e = i >> 6, n_e = i & 63;
                int ak  = ak0 + r_e;
                int a   = ak / KG;
                int kk  = ak - a * KG;
                float b  = bw[a * KG + kk];
                float wc = aw[a * KG + kk];
                float cc = (axis == 0) ? rgf[n_e * 12288]
                         : (axis == 1) ? rgf[n_e * 192 + 1]
                                       : rgf[n_e * 3 + 2];
                float d  = cc - X[a * 3 + axis];
                float v  = __expf(b * d * d);
                if (axis == 0) v *= wc;
                U.a.R[r_e * 64 + n_e] = v;
            }
            __syncthreads();
            if (tid < 272) {                             // 16 rows x 17 k
                int r = tid / 17, k = tid - r * 17;
                float2 ae = make_float2(0.f, 0.f), ao = ae;
                #pragma unroll
                for (int m = 0; m < 64; m += 2) {
                    float  x0 = U.a.R[r * 64 + m];
                    float  x1 = U.a.R[r * 64 + m + 1];
                    float2 w0 = Wsh[(k * m) & 63];
                    float2 w1 = Wsh[(k * (m + 1)) & 63];
                    ae.x = fmaf(x0, w0.x, ae.x); ae.y = fmaf(x0, w0.y, ae.y);
                    ao.x = fmaf(x1, w1.x, ao.x); ao.y = fmaf(x1, w1.y, ao.y);
                }
                U.a.T[r * 34 + k] = make_float2(ae.x + ao.x, ae.y + ao.y);
            }
            __syncthreads();
            // stores: 33 slots x 16 rows = 528 entries
            for (int i = tid; i < 528; i += 512) {
                if (axis == 0) {        // transposed centered: [ak][sxs]
                    int dak = i / 33, j = i - dak * 33;  // j = sxs
                    float2 t;
                    if (j >= 16) t = U.a.T[dak * 34 + (j - 16)];
                    else {
                        float2 s = U.a.T[dak * 34 + (16 - j)];
                        t = make_float2(s.x, -s.y);
                    }
                    g_FtX[(ak0 + dak) * 34 + j] = t;
                } else {                // [k][ak] with conj mirror
                    int dak = i & 15, j = i >> 4;        // j = 0..32
                    float2 t; int ks;
                    if (j <= 16) { t = U.a.T[dak * 34 + j]; ks = j; }
                    else {
                        float2 s = U.a.T[dak * 34 + (33 - j)];
                        t = make_float2(s.x, -s.y); ks = j + 31;
                    }
                    g_Ft[(axis - 1) * (N64 * AK) + ks * AK + ak0 + dak] = t;
                }
            }
            __syncthreads();
        }
    }
    gbar(0);

    // ===== Phase B: live-column spectrum + Hamming + weighted x-inverse =====
    {
        int NC, Lbase;
        if (bid < 74) { NC = 2; Lbase = bid * 2; }           // L 0..147
        else          { NC = 4; Lbase = 148 + (bid - 74) * 4; } // L 148..399
        if (tid < NC) {
            int L = Lbase + tid; if (L > NLIVE - 1) L = NLIVE - 1;
            int kzs = 0;
            while (c_row0[kzs + 1] <= L) kzs++;
            int off = L - c_row0[kzs];
            int w   = c_row0[kzs + 1] - c_row0[kzs];
            int kys = (kzs == 16) ? off : (16 - (w - 1) / 2 + off);
            colKys[tid] = kys;             colKzs[tid] = kzs;
            colKyi[tid] = (kys - 16) & 63; colKzi[tid] = (kzs - 16) & 63;
            colWt[tid]  = (L == NLIVE - 1) ? 1.f : 2.f;   // Hermitian weight
        }
        __syncthreads();

        // P = Fy * Fz staged once (coalesced global reads)
        for (int i = tid; i < NC * 768; i += 512) {
            int col = i / 768, a = i - col * 768;
            float2 fa = g_Ft[colKyi[col] * AK + a];
            float2 fb = g_Ft[N64 * AK + colKzi[col] * AK + a];
            U.b.P[col * 768 + a] = make_float2(fa.x * fb.x - fa.y * fb.y,
                                               fa.x * fb.y + fa.y * fb.x);
        }
        __syncthreads();

        int w    = tid >> 5, lane = tid & 31;
        int npairs = NC >> 1;                // 1 or 2 column pairs
        int wpp  = 16 / npairs;              // warps per pair: 16 or 8
        int pairw = w / wpp;
        int q    = w - pairw * wpp;
        int akpw = 768 / wpp;                // 48 or 96 aks per warp
        int base = q * akpw;
        float2 Sa0 = make_float2(0.f, 0.f), Sb0 = Sa0, Sa1 = Sa0, Sb1 = Sa0;
        float2 S20 = Sa0, S21 = Sa0;

        {
            const float2* P0 = &U.b.P[(pairw * 2 + 0) * 768 + base];
            const float2* P1 = &U.b.P[(pairw * 2 + 1) * 768 + base];
            const float2* Fr = &g_FtX[base * 34 + lane];
            if (npairs == 1) dot2<48>(P0, P1, Fr, Sa0, Sb0, Sa1, Sb1);
            else             dot2<96>(P0, P1, Fr, Sa0, Sb0, Sa1, Sb1);
            // sxs = 32 slice, lane-parallel over this warp's ak range
            for (int i = lane; i < akpw; i += 32) {
                float2 f = g_FtX[(base + i) * 34 + 32];
                float2 p0 = P0[i], p1 = P1[i];
                CMAC(S20, p0, f);
                CMAC(S21, p1, f);
            }
        }
        #pragma unroll
        for (int o = 16; o; o >>= 1) {
            S20.x += __shfl_xor_sync(0xFFFFFFFFu, S20.x, o);
            S20.y += __shfl_xor_sync(0xFFFFFFFFu, S20.y, o);
            S21.x += __shfl_xor_sync(0xFFFFFFFFu, S21.x, o);
            S21.y += __shfl_xor_sync(0xFFFFFFFFu, S21.y, o);
        }
        U.b.Sp[w * 66 + lane]      = make_float2(Sa0.x + Sb0.x, Sa0.y + Sb0.y);
        U.b.Sp[w * 66 + 33 + lane] = make_float2(Sa1.x + Sb1.x, Sa1.y + Sb1.y);
        if (lane == 0) {
            U.b.Sp[w * 66 + 32]      = S20;
            U.b.Sp[w * 66 + 33 + 32] = S21;
        }
        __syncthreads();

        // combine warp partials per column + Hamming + Parseval stats
        float2 v = make_float2(0.f, 0.f);
        int colc = 0, sxsc = 0;
        if (tid < NC * NS) {
            colc = tid / NS; sxsc = tid - colc * NS;
            int pair = colc >> 1, cip = colc & 1;
            float2 acc = make_float2(0.f, 0.f);
            for (int i = 0; i < wpp; i++) {
                float2 t = U.b.Sp[(pair * wpp + i) * 66 + cip * 33 + sxsc];
                acc.x += t.x; acc.y += t.y;
            }
            int kys = colKys[colc], kzs = colKzs[colc];
            int hx = (sxsc + 16) & 63, hy = (kys + 16) & 63, hz = (kzs + 16) & 63;
            float h = ham[(hx << 12) | (hy << 6) | hz];
            v = make_float2(acc.x * h, acc.y * h);
            int slotL = Lbase + colc;                 // un-clamped: stats guard
            double contrib = 0.0;
            if (slotL < NLIVE) {
                double m2 = (double)v.x * v.x + (double)v.y * v.y;
                contrib = (slotL == NLIVE - 1) ? m2 : 2.0 * m2;
                if (slotL == NLIVE - 1 && sxsc == 16) g_sum = (double)v.x;
            }
            U.b.Sred[tid] = contrib;
        }
        __syncthreads();
        if (tid < NC * NS) U.b.Sp[colc * NS + sxsc] = v;
        if (tid == 0) {
            double t = 0.0;
            for (int i = 0; i < NC * NS; i++) t += U.b.Sred[i];
            atomicAdd(&g_sumsq, t);
        }
        __syncthreads();

        // fused x-inverse (rotation twiddles), Hermitian weight pre-folded
        if (tid < NC * 64) {
            int col = tid >> 6, x = tid & 63;
            float2 T  = make_float2(0.f, 0.f);
            float2 wv = Wsh[(16 * x) & 63];      // s = -16 start
            float2 ws = Wsh[(-x) & 63];          // step: * e^{+2pi i x/64}
            #pragma unroll
            for (int sxs = 0; sxs < NS; sxs++) {
                float2 s = U.b.Sp[col * NS + sxs];
                T.x = fmaf(s.x, wv.x, T.x); T.x = fmaf(-s.y, wv.y, T.x);
                T.y = fmaf(s.x, wv.y, T.y); T.y = fmaf( s.y, wv.x, T.y);
                float2 nw = make_float2(wv.x * ws.x - wv.y * ws.y,
                                        wv.x * ws.y + wv.y * ws.x);
                wv = nw;
            }
            float wt = colWt[col];
            g_A[colKzs[col] * 2176 + x * 34 + colKys[col]] =
                make_float2(T.x * wt, T.y * wt);
        }
    }
    gbar(1);

    // ===== Phase C: folded half-plane y/z-inverse + normalized write ========
    // out = Re sum_{kzs=0..16} C[kzs][y] e^{+2pi i z (kzs-16)/64},
    // C[kzs][y] = sum_kys Aw[kzs][kys] e^{+2pi i y (kys-16)/64}  (Aw weighted)
    if (bid < 128) {
        int x = bid >> 1, yh = bid & 1;
        for (int i = tid; i < 17 * 33; i += 512) {
            int kzs = i / 33, kys = i - kzs * 33;
            U.c.A[i] = g_A[kzs * 2176 + x * 34 + kys];
        }
        __syncthreads();

        for (int i = tid; i < 17 * 32; i += 512) {   // y-inverse (544 entries)
            int yl = i & 31, kzs = i >> 5;
            int y  = yh * 32 + yl;
            float2 acc = make_float2(0.f, 0.f);
            float2 wv  = Wsh[(16 * y) & 63];
            float2 ws  = Wsh[(-y) & 63];
            #pragma unroll
            for (int kys = 0; kys < NS; kys++) {
                float2 a = U.c.A[kzs * 33 + kys];
                acc.x = fmaf(a.x, wv.x, acc.x); acc.x = fmaf(-a.y, wv.y, acc.x);
                acc.y = fmaf(a.x, wv.y, acc.y); acc.y = fmaf( a.y, wv.x, acc.y);
                float2 nw = make_float2(wv.x * ws.x - wv.y * ws.y,
                                        wv.x * ws.y + wv.y * ws.x);
                wv = nw;
            }
            U.c.C[kzs * 32 + yl] = acc;
        }
        __syncthreads();

        // Parseval stats: mean = S[0]/G;  E[out^2] = sum|S|^2 / G^2
        double mean = g_sum / (double)G;
        double var  = g_sumsq / ((double)G * (double)G) - mean * mean;
        double stdv = sqrt(var > 0.0 ? var : 0.0);
        float  inv  = (float)(1.0 / (stdv + 1e-8));
        float  m    = (float)mean;

        int z = tid & 63, yg = tid >> 6;     // 8 y-groups of 4
        float acc4[4];
        #pragma unroll
        for (int j = 0; j < 4; j++) acc4[j] = 0.f;
        float2 wv = Wsh[(16 * z) & 63];
        float2 ws = Wsh[(-z) & 63];
        for (int kzs = 0; kzs <= 16; kzs++) {        // folded z-inverse, Re
            #pragma unroll
            for (int j = 0; j < 4; j++) {
                float2 c = U.c.C[kzs * 32 + yg * 4 + j];
                acc4[j] = fmaf(c.x, wv.x, acc4[j]);
                acc4[j] = fmaf(-c.y, wv.y, acc4[j]);
            }
            float2 nw = make_float2(wv.x * ws.x - wv.y * ws.y,
                                    wv.x * ws.y + wv.y * ws.x);
            wv = nw;
        }
        const float scale = 1.0f / 262144.0f;        // ortho*ortho = 1/N^3
        #pragma unroll
        for (int j = 0; j < 4; j++) {
            float vv = acc4[j] * scale;
            int y = yh * 32 + yg * 4 + j;
            out[x * 4096 + y * 64 + z] = (vv - m) * inv;
        }
    }
}

// ---------------------------------------------------------------------------
// Launch
//   inputs: 0=X(384) 1=aw(768) 2=bw(768) 3=real_grid_flat(786432) 4=hamming(262144)
// ---------------------------------------------------------------------------
extern "C" void kernel_launch(void* const* d_in, const int* in_sizes, int n_in,
                              void* d_out, int out_size)
{
    const float* X   = (const float*)d_in[0];
    const float* aw  = (const float*)d_in[1];
    const float* bw  = (const float*)d_in[2];
    const float* rgf = (const float*)d_in[3];
    const float* ham = (const float*)d_in[4];

    k_all<<<NB, 512>>>(X, aw, bw, rgf, ham, (float*)d_out);
}

// round 17
// speedup vs baseline: 1.3226x; 1.1574x over previous
#include <cuda_runtime.h>
#include <math.h>

// ---------------------------------------------------------------------------
// Problem constants
// ---------------------------------------------------------------------------
#define N64    64
#define G      262144     // 64^3
#define KG     6
#define AK     768        // NATOM*KG
#define NS     33         // surviving frequencies per axis: s in [-16,16]
#define NLIVE  399        // live (ky,kz) half-columns: sy^2+sz^2 <= 256
#define NB     137        // persistent grid, 1 block/SM, all co-resident

// ---------------------------------------------------------------------------
// Device scratch (static globals: no allocation allowed)
// ---------------------------------------------------------------------------
__device__ float2 g_FtX[AK * 34];      // x-axis DFT, TRANSPOSED: [ak][sxs 0..32]
__device__ float2 g_Ft [2 * N64 * AK]; // y,z-axis DFTs: [axis][k][ak]
__device__ float2 g_A  [17 * 64 * 34]; // weighted x-inverse: [kzs<=16][x][kys]
                                       // dead entries never written (zero-init)
__device__ double g_sum, g_sumsq;      // spectral-domain stats (Parseval)
__device__ unsigned int          g_cnt[2];
__device__ volatile unsigned int g_gen[2];

// Live half-column enumeration: row kzs spans [c_row0[kzs], c_row0[kzs+1]).
// Row widths (kzs=0..15): 1,11,15,19,21,23,25,27,27,29,29,31,31,31,31,31;
// kzs=16 holds 17 (kys=0..16). Total 399. L=398 is the DC column (16,16).
__constant__ int c_row0[18] =
    {0,1,12,27,46,67,90,115,142,169,198,227,258,289,320,351,382,399};

// Shared-memory union: phases strictly sequential (grid barriers between).
union SmemU {
    struct { float  R[17 * 64]; float2 T[17 * 34]; } a;  // phase A
    struct { float2 P [3 * 768];                         // phase B: [col][ak]
             float2 Sp[16 * 99];    // per-warp partials: [w][col 0..2][33]
             double Sred[3 * NS]; } b;
    struct { float2 A[17 * 33]; float2 C[17 * 32]; } c;  // phase C
};

// Replay-safe grid barrier (counter self-resets via atomicInc wrap).
__device__ __forceinline__ void gbar(int i)
{
    __threadfence();
    __syncthreads();
    if (threadIdx.x == 0) {
        unsigned int my = g_gen[i];
        unsigned int t = atomicInc(&g_cnt[i], NB - 1);
        if (t == NB - 1) { __threadfence(); g_gen[i] = my + 1; }
        else             { while (g_gen[i] == my) __nanosleep(64); }
        __threadfence();
    }
    __syncthreads();
}

#define CMAC(S, p, f)                                             \
    do {                                                          \
        (S).x = fmaf((p).x, (f).x, (S).x);                        \
        (S).x = fmaf(-(p).y, (f).y, (S).x);                       \
        (S).y = fmaf((p).x, (f).y, (S).y);                        \
        (S).y = fmaf((p).y, (f).x, (S).y);                        \
    } while (0)

// Triple-column complex dot: AKPW aks, ONE Fx load stream (coalesced,
// stride-34 rows, lane = kx slot) feeds THREE column accumulations.
template <int AKPW>
__device__ __forceinline__ void dot3(const float2* __restrict__ P0,
                                     const float2* __restrict__ P1,
                                     const float2* __restrict__ P2,
                                     const float2* __restrict__ Fr,
                                     float2& S0, float2& S1, float2& S2c)
{
    #pragma unroll 4
    for (int i = 0; i < AKPW; i++) {
        float2 f  = Fr[i * 34];
        float2 p0 = P0[i], p1 = P1[i], p2 = P2[i];
        CMAC(S0, p0, f);
        CMAC(S1, p1, f);
        CMAC(S2c, p2, f);
    }
}

// ---------------------------------------------------------------------------
// Whole pipeline, one persistent kernel, 1 block/SM (no register cap).
// ---------------------------------------------------------------------------
__global__ void __launch_bounds__(512, 1)
k_all(const float* __restrict__ X,  const float* __restrict__ aw,
      const float* __restrict__ bw, const float* __restrict__ rgf,
      const float* __restrict__ ham, float* __restrict__ out)
{
    __shared__ SmemU U;
    __shared__ float2 Wsh[64];
    __shared__ int   colKys[3], colKzs[3], colKyi[3], colKzi[3];
    __shared__ float colWt[3];

    int tid = threadIdx.x, bid = blockIdx.x;

    if (tid < 64) {
        float ang = -2.0f * 3.14159265358979323846f * (float)tid / 64.0f;
        float s, c;
        __sincosf(ang, &s, &c);
        Wsh[tid] = make_float2(c, s);
    }
    if (bid == 0 && tid == 0) g_sumsq = 0.0;
    __syncthreads();

    // ===== Phase A: tables -> 17-pt real DFT -> g_FtX / g_Ft ================
    // 136 groups of 17 rows (per-row axis decode): EXACTLY one group/block.
    if (bid < 136) {
        int row0 = bid * 17;
        for (int i = tid; i < 1088; i += 512) {      // exp: 17 rows x 64
            int r_e = i >> 6, n_e = i & 63;
            int row = row0 + r_e;
            if (row < 2304) {
                int axis = row / 768;
                int ak   = row - axis * 768;
                int a    = ak / KG;
                int kk   = ak - a * KG;
                float b  = bw[a * KG + kk];
                float wc = aw[a * KG + kk];
                float cc = (axis == 0) ? rgf[n_e * 12288]
                         : (axis == 1) ? rgf[n_e * 192 + 1]
                                       : rgf[n_e * 3 + 2];
                float d  = cc - X[a * 3 + axis];
                float v  = __expf(b * d * d);
                if (axis == 0) v *= wc;
                U.a.R[r_e * 64 + n_e] = v;
            }
        }
        __syncthreads();
        if (tid < 289) {                             // 17 rows x 17 k
            int r = tid / 17, k = tid - r * 17;
            if (row0 + r < 2304) {
                float2 ae = make_float2(0.f, 0.f), ao = ae;
                #pragma unroll
                for (int m = 0; m < 64; m += 2) {
                    float  x0 = U.a.R[r * 64 + m];
                    float  x1 = U.a.R[r * 64 + m + 1];
                    float2 w0 = Wsh[(k * m) & 63];
                    float2 w1 = Wsh[(k * (m + 1)) & 63];
                    ae.x = fmaf(x0, w0.x, ae.x); ae.y = fmaf(x0, w0.y, ae.y);
                    ao.x = fmaf(x1, w1.x, ao.x); ao.y = fmaf(x1, w1.y, ao.y);
                }
                U.a.T[r * 34 + k] = make_float2(ae.x + ao.x, ae.y + ao.y);
            }
        }
        __syncthreads();
        // stores: 33 slots x 17 rows = 561 entries (j-major for Ft coalescing)
        for (int i = tid; i < 561; i += 512) {
            int j = i / 17, r = i - j * 17;          // j = 0..32
            int row = row0 + r;
            if (row < 2304) {
                int axis = row / 768;
                int ak   = row - axis * 768;
                if (axis == 0) {        // transposed centered: [ak][sxs]
                    float2 t;
                    if (j >= 16) t = U.a.T[r * 34 + (j - 16)];
                    else {
                        float2 s = U.a.T[r * 34 + (16 - j)];
                        t = make_float2(s.x, -s.y);
                    }
                    g_FtX[ak * 34 + j] = t;
                } else {                // [k][ak] with conj mirror
                    float2 t; int ks;
                    if (j <= 16) { t = U.a.T[r * 34 + j]; ks = j; }
                    else {
                        float2 s = U.a.T[r * 34 + (33 - j)];
                        t = make_float2(s.x, -s.y); ks = j + 31;
                    }
                    g_Ft[(axis - 1) * (N64 * AK) + ks * AK + ak] = t;
                }
            }
        }
    }
    gbar(0);

    // ===== Phase B: 3 columns/block, Hamming + weighted x-inverse ===========
    if (bid < 133) {
        int Lbase = bid * 3;                          // 133*3 = 399 exactly
        if (tid < 3) {
            int L = Lbase + tid;
            int kzs = 0;
            while (c_row0[kzs + 1] <= L) kzs++;
            int off = L - c_row0[kzs];
            int w   = c_row0[kzs + 1] - c_row0[kzs];
            int kys = (kzs == 16) ? off : (16 - (w - 1) / 2 + off);
            colKys[tid] = kys;             colKzs[tid] = kzs;
            colKyi[tid] = (kys - 16) & 63; colKzi[tid] = (kzs - 16) & 63;
            colWt[tid]  = (L == NLIVE - 1) ? 1.f : 2.f;   // Hermitian weight
        }
        __syncthreads();

        // P = Fy * Fz staged once (coalesced global reads)
        for (int i = tid; i < 3 * 768; i += 512) {
            int col = i / 768, a = i - col * 768;
            float2 fa = g_Ft[colKyi[col] * AK + a];
            float2 fb = g_Ft[N64 * AK + colKzi[col] * AK + a];
            U.b.P[col * 768 + a] = make_float2(fa.x * fb.x - fa.y * fb.y,
                                               fa.x * fb.y + fa.y * fb.x);
        }
        __syncthreads();

        int w = tid >> 5, lane = tid & 31;
        int base = w * 48;                            // 16 warps x 48 aks
        float2 S0 = make_float2(0.f, 0.f), S1 = S0, S2c = S0;
        float2 T0 = S0, T1 = S0, T2 = S0;             // kx=32 tails

        {
            const float2* P0 = &U.b.P[0 * 768 + base];
            const float2* P1 = &U.b.P[1 * 768 + base];
            const float2* P2 = &U.b.P[2 * 768 + base];
            const float2* Fr = &g_FtX[base * 34 + lane];
            dot3<48>(P0, P1, P2, Fr, S0, S1, S2c);
            // sxs = 32 slice, lane-parallel over this warp's ak range
            for (int i = lane; i < 48; i += 32) {
                float2 f = g_FtX[(base + i) * 34 + 32];
                float2 p0 = P0[i], p1 = P1[i], p2 = P2[i];
                CMAC(T0, p0, f);
                CMAC(T1, p1, f);
                CMAC(T2, p2, f);
            }
        }
        #pragma unroll
        for (int o = 16; o; o >>= 1) {
            T0.x += __shfl_xor_sync(0xFFFFFFFFu, T0.x, o);
            T0.y += __shfl_xor_sync(0xFFFFFFFFu, T0.y, o);
            T1.x += __shfl_xor_sync(0xFFFFFFFFu, T1.x, o);
            T1.y += __shfl_xor_sync(0xFFFFFFFFu, T1.y, o);
            T2.x += __shfl_xor_sync(0xFFFFFFFFu, T2.x, o);
            T2.y += __shfl_xor_sync(0xFFFFFFFFu, T2.y, o);
        }
        U.b.Sp[w * 99 +      lane] = S0;
        U.b.Sp[w * 99 + 33 + lane] = S1;
        U.b.Sp[w * 99 + 66 + lane] = S2c;
        if (lane == 0) {
            U.b.Sp[w * 99 + 32] = T0;
            U.b.Sp[w * 99 + 65] = T1;
            U.b.Sp[w * 99 + 98] = T2;
        }
        __syncthreads();

        // combine 16 warp partials per column + Hamming + Parseval stats
        float2 v = make_float2(0.f, 0.f);
        int colc = 0, sxsc = 0;
        if (tid < 3 * NS) {
            colc = tid / NS; sxsc = tid - colc * NS;
            float2 acc = make_float2(0.f, 0.f);
            #pragma unroll
            for (int i = 0; i < 16; i++) {
                float2 t = U.b.Sp[i * 99 + colc * 33 + sxsc];
                acc.x += t.x; acc.y += t.y;
            }
            int kys = colKys[colc], kzs = colKzs[colc];
            int hx = (sxsc + 16) & 63, hy = (kys + 16) & 63, hz = (kzs + 16) & 63;
            float h = ham[(hx << 12) | (hy << 6) | hz];
            v = make_float2(acc.x * h, acc.y * h);
            int L = Lbase + colc;
            double m2 = (double)v.x * v.x + (double)v.y * v.y;
            U.b.Sred[tid] = (L == NLIVE - 1) ? m2 : 2.0 * m2;   // Hermitian wt
            if (L == NLIVE - 1 && sxsc == 16) g_sum = (double)v.x;  // S(0,0,0)
        }
        __syncthreads();
        if (tid < 3 * NS) U.b.Sp[colc * NS + sxsc] = v;
        if (tid == 0) {
            double t = 0.0;
            for (int i = 0; i < 3 * NS; i++) t += U.b.Sred[i];
            atomicAdd(&g_sumsq, t);
        }
        __syncthreads();

        // fused x-inverse (rotation twiddles), Hermitian weight pre-folded
        if (tid < 3 * 64) {
            int col = tid >> 6, x = tid & 63;
            float2 T  = make_float2(0.f, 0.f);
            float2 wv = Wsh[(16 * x) & 63];      // s = -16 start
            float2 ws = Wsh[(-x) & 63];          // step: * e^{+2pi i x/64}
            #pragma unroll
            for (int sxs = 0; sxs < NS; sxs++) {
                float2 s = U.b.Sp[col * NS + sxs];
                T.x = fmaf(s.x, wv.x, T.x); T.x = fmaf(-s.y, wv.y, T.x);
                T.y = fmaf(s.x, wv.y, T.y); T.y = fmaf( s.y, wv.x, T.y);
                float2 nw = make_float2(wv.x * ws.x - wv.y * ws.y,
                                        wv.x * ws.y + wv.y * ws.x);
                wv = nw;
            }
            float wt = colWt[col];
            g_A[colKzs[col] * 2176 + x * 34 + colKys[col]] =
                make_float2(T.x * wt, T.y * wt);
        }
    }
    gbar(1);

    // ===== Phase C: folded half-plane y/z-inverse + normalized write ========
    // out = Re sum_{kzs=0..16} C[kzs][y] e^{+2pi i z (kzs-16)/64},
    // C[kzs][y] = sum_kys Aw[kzs][kys] e^{+2pi i y (kys-16)/64}  (Aw weighted)
    if (bid < 128) {
        int x = bid >> 1, yh = bid & 1;
        for (int i = tid; i < 17 * 33; i += 512) {
            int kzs = i / 33, kys = i - kzs * 33;
            U.c.A[i] = g_A[kzs * 2176 + x * 34 + kys];
        }
        __syncthreads();

        for (int i = tid; i < 17 * 32; i += 512) {   // y-inverse (544 entries)
            int yl = i & 31, kzs = i >> 5;
            int y  = yh * 32 + yl;
            float2 acc = make_float2(0.f, 0.f);
            float2 wv  = Wsh[(16 * y) & 63];
            float2 ws  = Wsh[(-y) & 63];
            #pragma unroll
            for (int kys = 0; kys < NS; kys++) {
                float2 a = U.c.A[kzs * 33 + kys];
                acc.x = fmaf(a.x, wv.x, acc.x); acc.x = fmaf(-a.y, wv.y, acc.x);
                acc.y = fmaf(a.x, wv.y, acc.y); acc.y = fmaf( a.y, wv.x, acc.y);
                float2 nw = make_float2(wv.x * ws.x - wv.y * ws.y,
                                        wv.x * ws.y + wv.y * ws.x);
                wv = nw;
            }
            U.c.C[kzs * 32 + yl] = acc;
        }
        __syncthreads();

        // Parseval stats: mean = S[0]/G;  E[out^2] = sum|S|^2 / G^2
        double mean = g_sum / (double)G;
        double var  = g_sumsq / ((double)G * (double)G) - mean * mean;
        double stdv = sqrt(var > 0.0 ? var : 0.0);
        float  inv  = (float)(1.0 / (stdv + 1e-8));
        float  m    = (float)mean;

        int z = tid & 63, yg = tid >> 6;     // 8 y-groups of 4
        float acc4[4];
        #pragma unroll
        for (int j = 0; j < 4; j++) acc4[j] = 0.f;
        float2 wv = Wsh[(16 * z) & 63];
        float2 ws = Wsh[(-z) & 63];
        for (int kzs = 0; kzs <= 16; kzs++) {        // folded z-inverse, Re
            #pragma unroll
            for (int j = 0; j < 4; j++) {
                float2 c = U.c.C[kzs * 32 + yg * 4 + j];
                acc4[j] = fmaf(c.x, wv.x, acc4[j]);
                acc4[j] = fmaf(-c.y, wv.y, acc4[j]);
            }
            float2 nw = make_float2(wv.x * ws.x - wv.y * ws.y,
                                    wv.x * ws.y + wv.y * ws.x);
            wv = nw;
        }
        const float scale = 1.0f / 262144.0f;        // ortho*ortho = 1/N^3
        #pragma unroll
        for (int j = 0; j < 4; j++) {
            float vv = acc4[j] * scale;
            int y = yh * 32 + yg * 4 + j;
            out[x * 4096 + y * 64 + z] = (vv - m) * inv;
        }
    }
}

// ---------------------------------------------------------------------------
// Launch
//   inputs: 0=X(384) 1=aw(768) 2=bw(768) 3=real_grid_flat(786432) 4=hamming(262144)
// ---------------------------------------------------------------------------
extern "C" void kernel_launch(void* const* d_in, const int* in_sizes, int n_in,
                              void* d_out, int out_size)
{
    const float* X   = (const float*)d_in[0];
    const float* aw  = (const float*)d_in[1];
    const float* bw  = (const float*)d_in[2];
    const float* rgf = (const float*)d_in[3];
    const float* ham = (const float*)d_in[4];

    k_all<<<NB, 512>>>(X, aw, bw, rgf, ham, (float*)d_out);
}